// round 13
// baseline (speedup 1.0000x reference)
#include <cuda_runtime.h>
#include <cstdint>

// dct: [16, 64, 256, 256] fp32, mean/std: [64] fp32, out: [16, 1, 2048, 2048] fp32
#define HW       65536       // 256*256
#define OUTW     2048
#define BSTRIDE  132         // padded row stride (floats) -> conflict-free cp.async stores

// Dynamic smem (floats): buf [64 ch][BSTRIDE] + tables
#define BUF_FLOATS   (64 * BSTRIDE)
#define SMEM_FLOATS  (BUF_FLOATS + 192)
#define SMEM_BYTES   (SMEM_FLOATS * 4)

__device__ __forceinline__ void cp_async16(uint32_t dst, const void* src) {
    asm volatile("cp.async.cg.shared.global [%0], [%1], 16;" :: "r"(dst), "l"(src));
}
__device__ __forceinline__ void cp_commit() {
    asm volatile("cp.async.commit_group;");
}
template <int N>
__device__ __forceinline__ void cp_wait() {
    asm volatile("cp.async.wait_group %0;" :: "n"(N) : "memory");
}

// Consume chunk U (channels U*8..U*8+7). Only threads whose parity matches
// U's parity do work (disjoint channel sets per pair; E vs O accumulators).
template <int U>
__device__ __forceinline__ void consume_chunk(
    const float* buf, const float* s_hx, const float* s_hy,
    const float* s_std, const float* s_mean,
    int tid, float acc[4][8])
{
    cp_wait<7 - U>();
    __syncwarp();     // warp-private stripes: warp-local visibility suffices

    if ((tid & 1) == (U & 1)) {
        int pl = tid >> 1;        // 0..127: position within CTA tile
        float t[8];
        #pragma unroll
        for (int v = 0; v < 8; v++)
            t[v] = buf[(U * 8 + v) * BSTRIDE + pl];
        #pragma unroll
        for (int v = 0; v < 8; v++)
            t[v] = fmaf(t[v], s_std[U * 8 + v], s_mean[U * 8 + v]);

        // y-pass (v -> y) with even/odd-v butterfly
        float ty[8];
        #pragma unroll
        for (int yp = 0; yp < 4; yp++) {
            float te = 0.0f, to = 0.0f;
            #pragma unroll
            for (int vp = 0; vp < 4; vp++) {
                te = fmaf(s_hy[(2 * vp    ) * 4 + yp], t[2 * vp    ], te);
                to = fmaf(s_hy[(2 * vp + 1) * 4 + yp], t[2 * vp + 1], to);
            }
            ty[yp]     = te + to;
            ty[7 - yp] = te - to;
        }

        // x-pass partial accumulation into this thread's parity accumulator
        #pragma unroll
        for (int xp = 0; xp < 4; xp++) {
            float w = s_hx[U * 4 + xp];
            #pragma unroll
            for (int y = 0; y < 8; y++)
                acc[xp][y] = fmaf(w, ty[y], acc[xp][y]);
        }
    }
}

__global__ __launch_bounds__(256, 3) void idct_kernel(
    const float* __restrict__ dct,
    const float* __restrict__ mean_,
    const float* __restrict__ std_,
    float* __restrict__ out)
{
    extern __shared__ float smem[];
    float* buf    = smem;                      // [64][BSTRIDE]
    float* s_hx   = smem + BUF_FLOATS;         // [8][4]
    float* s_hy   = s_hx + 32;                 // [8][4]
    float* s_std  = s_hy + 32;                 // [64]
    float* s_mean = s_std + 64;                // [64]

    int tid  = threadIdx.x;
    int warp = tid >> 5, lane = tid & 31;
    uint32_t sb = (uint32_t)__cvta_generic_to_shared(buf);

    // CTA covers 128 consecutive positions (tiles never straddle a batch).
    unsigned ctapos = blockIdx.x * 128u;          // 0 .. 1M-1
    unsigned b      = ctapos >> 16;
    unsigned posb   = ctapos & 65535u;
    // Warp-uniform source: warp w owns positions [16w, 16w+16).
    const float* src_w = dct + (size_t)b * 64u * HW + posb + warp * 16u;

    // ---- Warp-private full prefetch: 8 chunks, one cp.async per lane each.
    // Lane covers channel c*8 + (lane>>2), 16B at float col (lane&3)*4 of the
    // warp's 16-position stripe (64B contiguous per channel per warp). ----
    #pragma unroll
    for (int c = 0; c < 8; c++) {
        int ch = c * 8 + (lane >> 2);
        const float* g = src_w + (size_t)ch * HW + (lane & 3) * 4;
        cp_async16(sb + (uint32_t)((ch * BSTRIDE + warp * 16 + (lane & 3) * 4) * 4), g);
        cp_commit();
    }

    // ---- Tables (overlap with copies); one barrier, doesn't drain groups ----
    if (tid < 64) {
        int u = tid >> 3, x = tid & 7;
        float c = (u == 0) ? 0.70710678118654752440f : 1.0f;
        float h = cospif((float)((2 * x + 1) * u) * (1.0f / 16.0f));
        float v = 0.5f * c * h;
        if (x < 4) {
            s_hx[u * 4 + x] = v;
            s_hy[u * 4 + x] = v * (1.0f / 255.0f);
        }
        s_std[tid]  = std_[tid];
        s_mean[tid] = mean_[tid];
    }
    __syncthreads();

    // Accumulator: even thread -> E (init K), odd thread -> O (init 0).
    const float K = 128.0f / 255.0f;
    int parity = tid & 1;
    float init = parity ? 0.0f : K;
    float acc[4][8];
    #pragma unroll
    for (int xp = 0; xp < 4; xp++)
        #pragma unroll
        for (int y = 0; y < 8; y++) acc[xp][y] = init;

    consume_chunk<0>(buf, s_hx, s_hy, s_std, s_mean, tid, acc);
    consume_chunk<1>(buf, s_hx, s_hy, s_std, s_mean, tid, acc);
    consume_chunk<2>(buf, s_hx, s_hy, s_std, s_mean, tid, acc);
    consume_chunk<3>(buf, s_hx, s_hy, s_std, s_mean, tid, acc);
    consume_chunk<4>(buf, s_hx, s_hy, s_std, s_mean, tid, acc);
    consume_chunk<5>(buf, s_hx, s_hy, s_std, s_mean, tid, acc);
    consume_chunk<6>(buf, s_hx, s_hy, s_std, s_mean, tid, acc);
    consume_chunk<7>(buf, s_hx, s_hy, s_std, s_mean, tid, acc);

    // ---- Pair exchange + streaming stores: even lane rows 0..3 (E+O),
    // odd lane rows 7..4 (E-O). ----
    unsigned posg = ctapos + (unsigned)(tid >> 1);
    unsigned pos  = posg & 65535u;
    unsigned hh = pos >> 8, ww = pos & 255u;
    float* dst = out + (size_t)b * ((size_t)OUTW * OUTW)
                     + (size_t)hh * 8 * OUTW + (size_t)ww * 8;

    #pragma unroll
    for (int xp = 0; xp < 4; xp++) {
        float r[8];
        #pragma unroll
        for (int y = 0; y < 8; y++) {
            float q = __shfl_xor_sync(0xffffffffu, acc[xp][y], 1);
            r[y] = parity ? (q - acc[xp][y]) : (acc[xp][y] + q);
        }
        int row = parity ? (7 - xp) : xp;
        float4 a, bq;
        a.x  = r[0]; a.y  = r[1]; a.z  = r[2]; a.w  = r[3];
        bq.x = r[4]; bq.y = r[5]; bq.z = r[6]; bq.w = r[7];
        __stcs((float4*)(dst + (size_t)row * OUTW),     a);
        __stcs((float4*)(dst + (size_t)row * OUTW + 4), bq);
    }
}

extern "C" void kernel_launch(void* const* d_in, const int* in_sizes, int n_in,
                              void* d_out, int out_size)
{
    (void)in_sizes; (void)n_in; (void)out_size;
    const float* dct   = (const float*)d_in[0];
    const float* mean_ = (const float*)d_in[1];
    const float* std_  = (const float*)d_in[2];
    float* out = (float*)d_out;

    static bool attr_set = false;
    if (!attr_set) {
        cudaFuncSetAttribute(idct_kernel,
                             cudaFuncAttributeMaxDynamicSharedMemorySize,
                             SMEM_BYTES);
        attr_set = true;
    }
    // 1,048,576 blocks of 8x8 pixels, 2 threads per block, 128 blocks per CTA.
    idct_kernel<<<8192, 256, SMEM_BYTES>>>(dct, mean_, std_, out);
}

// round 15
// speedup vs baseline: 1.1960x; 1.1960x over previous
#include <cuda_runtime.h>
#include <cstdint>

// dct: [16, 64, 256, 256] fp32, mean/std: [64] fp32, out: [16, 1, 2048, 2048] fp32
#define HW       65536       // 256*256
#define OUTW     2048
#define BSTRIDE  132         // 16B-aligned rows (132*4 = 528 = 33*16)

// Row layout: channel ch lives at float offset ch*BSTRIDE + ((ch>>3)&1)*16.
// The +16-float (64B) pad on odd-u rows shifts them by 16 banks:
// 8*132 + 16 = 1072 = 16 (mod 32)  ->  even/odd lanes hit disjoint bank halves.
#define BUF_FLOATS   (64 * BSTRIDE + 16)
#define SMEM_FLOATS  (BUF_FLOATS + 192)
#define SMEM_BYTES   (SMEM_FLOATS * 4)

__device__ __forceinline__ int ch_off(int ch) {
    return ch * BSTRIDE + (((ch >> 3) & 1) << 4);
}

__device__ __forceinline__ void cp_async16(uint32_t dst, const void* src) {
    asm volatile("cp.async.cg.shared.global [%0], [%1], 16;" :: "r"(dst), "l"(src));
}
__device__ __forceinline__ void cp_commit() {
    asm volatile("cp.async.commit_group;");
}
template <int N>
__device__ __forceinline__ void cp_wait() {
    asm volatile("cp.async.wait_group %0;" :: "n"(N) : "memory");
}

// Consume chunk U = channels [16U, 16U+16): u = 2U (even lanes) / 2U+1 (odd
// lanes). ALL lanes active — no predication waste.
template <int U>
__device__ __forceinline__ void consume_chunk(
    const float* buf, const float* s_hx, const float* s_hy,
    const float* s_std, const float* s_mean,
    int tid, int parity, float acc[4][8])
{
    cp_wait<3 - U>();
    __syncwarp();     // warp-private stripes: warp-local visibility suffices

    int u  = 2 * U + parity;
    int pl = tid >> 1;            // position within CTA tile (0..127)

    float t[8];
    #pragma unroll
    for (int v = 0; v < 8; v++)
        t[v] = buf[ch_off(u * 8 + v) + pl];
    #pragma unroll
    for (int v = 0; v < 8; v++)
        t[v] = fmaf(t[v], s_std[u * 8 + v], s_mean[u * 8 + v]);

    // y-pass (v -> y) with even/odd-v butterfly
    float ty[8];
    #pragma unroll
    for (int yp = 0; yp < 4; yp++) {
        float te = 0.0f, to = 0.0f;
        #pragma unroll
        for (int vp = 0; vp < 4; vp++) {
            te = fmaf(s_hy[(2 * vp    ) * 4 + yp], t[2 * vp    ], te);
            to = fmaf(s_hy[(2 * vp + 1) * 4 + yp], t[2 * vp + 1], to);
        }
        ty[yp]     = te + to;
        ty[7 - yp] = te - to;
    }

    // x-pass partial accumulation for this lane's u
    #pragma unroll
    for (int xp = 0; xp < 4; xp++) {
        float w = s_hx[u * 4 + xp];
        #pragma unroll
        for (int y = 0; y < 8; y++)
            acc[xp][y] = fmaf(w, ty[y], acc[xp][y]);
    }
}

__global__ __launch_bounds__(256, 3) void idct_kernel(
    const float* __restrict__ dct,
    const float* __restrict__ mean_,
    const float* __restrict__ std_,
    float* __restrict__ out)
{
    extern __shared__ float smem[];
    float* buf    = smem;                      // padded [64][BSTRIDE] (+16)
    float* s_hx   = smem + BUF_FLOATS;         // [8][4]
    float* s_hy   = s_hx + 32;                 // [8][4]
    float* s_std  = s_hy + 32;                 // [64]
    float* s_mean = s_std + 64;                // [64]

    int tid  = threadIdx.x;
    int warp = tid >> 5, lane = tid & 31;
    uint32_t sb = (uint32_t)__cvta_generic_to_shared(buf);

    // CTA covers 128 consecutive positions (never straddles a batch).
    unsigned ctapos = blockIdx.x * 128u;       // 0 .. 1M-1
    unsigned b      = ctapos >> 16;
    unsigned posb   = ctapos & 65535u;
    // Warp w owns positions [16w, 16w+16) of the tile.
    const float* src_w = dct + (size_t)b * 64u * HW + posb + warp * 16u;

    // ---- Warp-private prefetch: 4 chunks x 16 channels. Per chunk, 64 x 16B
    // units, 2 per lane. Unit m: channel c*16 + (m>>2), float col (m&3)*4
    // within the warp's 16-position stripe. One commit group per chunk.
    // smem dst = (ch_off(ch) + warp*16 + (m&3)*4) floats — all 16B-aligned. ----
    #pragma unroll
    for (int c = 0; c < 4; c++) {
        #pragma unroll
        for (int k = 0; k < 2; k++) {
            int m  = lane + k * 32;
            int ch = c * 16 + (m >> 2);
            const float* g = src_w + (size_t)ch * HW + (m & 3) * 4;
            cp_async16(sb + (uint32_t)((ch_off(ch) + warp * 16 + (m & 3) * 4) * 4), g);
        }
        cp_commit();
    }

    // ---- Tables (overlap with copies); one barrier, doesn't drain groups ----
    if (tid < 64) {
        int u = tid >> 3, x = tid & 7;
        float c = (u == 0) ? 0.70710678118654752440f : 1.0f;
        float h = cospif((float)((2 * x + 1) * u) * (1.0f / 16.0f));
        float v = 0.5f * c * h;
        if (x < 4) {
            s_hx[u * 4 + x] = v;
            s_hy[u * 4 + x] = v * (1.0f / 255.0f);
        }
        s_std[tid]  = std_[tid];
        s_mean[tid] = mean_[tid];
    }
    __syncthreads();

    // Accumulator: even lane -> E (init K = 128/255), odd lane -> O (init 0).
    const float K = 128.0f / 255.0f;
    int parity = tid & 1;
    float init = parity ? 0.0f : K;
    float acc[4][8];
    #pragma unroll
    for (int xp = 0; xp < 4; xp++)
        #pragma unroll
        for (int y = 0; y < 8; y++) acc[xp][y] = init;

    consume_chunk<0>(buf, s_hx, s_hy, s_std, s_mean, tid, parity, acc);
    consume_chunk<1>(buf, s_hx, s_hy, s_std, s_mean, tid, parity, acc);
    consume_chunk<2>(buf, s_hx, s_hy, s_std, s_mean, tid, parity, acc);
    consume_chunk<3>(buf, s_hx, s_hy, s_std, s_mean, tid, parity, acc);

    // ---- Pair exchange + streaming stores: even lane rows 0..3 (E+O),
    // odd lane rows 7..4 (E-O). ----
    unsigned pos = (ctapos & 65535u) + (unsigned)(tid >> 1);
    unsigned hh = pos >> 8, ww = pos & 255u;
    float* dst = out + (size_t)b * ((size_t)OUTW * OUTW)
                     + (size_t)hh * 8 * OUTW + (size_t)ww * 8;

    #pragma unroll
    for (int xp = 0; xp < 4; xp++) {
        float r[8];
        #pragma unroll
        for (int y = 0; y < 8; y++) {
            float q = __shfl_xor_sync(0xffffffffu, acc[xp][y], 1);
            r[y] = parity ? (q - acc[xp][y]) : (acc[xp][y] + q);
        }
        int row = parity ? (7 - xp) : xp;
        float4 a, bq;
        a.x  = r[0]; a.y  = r[1]; a.z  = r[2]; a.w  = r[3];
        bq.x = r[4]; bq.y = r[5]; bq.z = r[6]; bq.w = r[7];
        __stcs((float4*)(dst + (size_t)row * OUTW),     a);
        __stcs((float4*)(dst + (size_t)row * OUTW + 4), bq);
    }
}

extern "C" void kernel_launch(void* const* d_in, const int* in_sizes, int n_in,
                              void* d_out, int out_size)
{
    (void)in_sizes; (void)n_in; (void)out_size;
    const float* dct   = (const float*)d_in[0];
    const float* mean_ = (const float*)d_in[1];
    const float* std_  = (const float*)d_in[2];
    float* out = (float*)d_out;

    static bool attr_set = false;
    if (!attr_set) {
        cudaFuncSetAttribute(idct_kernel,
                             cudaFuncAttributeMaxDynamicSharedMemorySize,
                             SMEM_BYTES);
        attr_set = true;
    }
    // 1,048,576 blocks of 8x8 pixels, 2 threads per block, 128 blocks per CTA.
    idct_kernel<<<8192, 256, SMEM_BYTES>>>(dct, mean_, std_, out);
}

// round 16
// speedup vs baseline: 1.2994x; 1.0865x over previous
#include <cuda_runtime.h>
#include <cstdint>

// dct: [16, 64, 256, 256] fp32, mean/std: [64] fp32, out: [16, 1, 2048, 2048] fp32
#define HW      65536        // 256*256
#define OUTW    2048

// CTA: 128 threads, 128 positions. Dynamic smem (floats):
//   sbuf [8 chunks][8 ch][128 pos] + tables
#define SBUF_FLOATS   8192
#define SMEM_FLOATS   (SBUF_FLOATS + 192)
#define SMEM_BYTES    (SMEM_FLOATS * 4)

__device__ __forceinline__ void cp_async16(uint32_t dst, const void* src) {
    asm volatile("cp.async.cg.shared.global [%0], [%1], 16;" :: "r"(dst), "l"(src));
}
__device__ __forceinline__ void cp_commit() {
    asm volatile("cp.async.commit_group;");
}
template <int N>
__device__ __forceinline__ void cp_wait() {
    asm volatile("cp.async.wait_group %0;" :: "n"(N) : "memory");
}

// Consume chunk U (warp-local ordering only: wait_group + syncwarp).
template <int U>
__device__ __forceinline__ void consume_chunk(
    const float* sbuf, const float* s_hx, const float* s_hy,
    const float* s_std, const float* s_mean,
    int tid, float E[4][8], float O[4][8])
{
    cp_wait<7 - U>();
    __syncwarp();      // cross-lane visibility within the warp's stripe

    float t[8];
    #pragma unroll
    for (int v = 0; v < 8; v++)
        t[v] = fmaf(sbuf[U * 1024 + v * 128 + tid],
                    s_std[U * 8 + v], s_mean[U * 8 + v]);

    float ty[8];
    #pragma unroll
    for (int yp = 0; yp < 4; yp++) {
        float te = 0.0f, to = 0.0f;
        #pragma unroll
        for (int vp = 0; vp < 4; vp++) {
            te = fmaf(s_hy[(2 * vp    ) * 4 + yp], t[2 * vp    ], te);
            to = fmaf(s_hy[(2 * vp + 1) * 4 + yp], t[2 * vp + 1], to);
        }
        ty[yp]     = te + to;
        ty[7 - yp] = te - to;
    }

    #pragma unroll
    for (int xp = 0; xp < 4; xp++) {
        float w = s_hx[U * 4 + xp];
        if ((U & 1) == 0) {
            #pragma unroll
            for (int y = 0; y < 8; y++) E[xp][y] = fmaf(w, ty[y], E[xp][y]);
        } else {
            #pragma unroll
            for (int y = 0; y < 8; y++) O[xp][y] = fmaf(w, ty[y], O[xp][y]);
        }
    }
}

__global__ __launch_bounds__(128, 4) void idct_kernel(
    const float* __restrict__ dct,
    const float* __restrict__ mean_,
    const float* __restrict__ std_,
    float* __restrict__ out)
{
    extern __shared__ float smem[];
    float* sbuf   = smem;                      // [8][8][128]
    float* s_hx   = smem + SBUF_FLOATS;        // [8][4]
    float* s_hy   = s_hx + 32;                 // [8][4]
    float* s_std  = s_hy + 32;                 // [64]
    float* s_mean = s_std + 64;                // [64]

    int tid  = threadIdx.x;
    int warp = tid >> 5, lane = tid & 31;

    unsigned gid = blockIdx.x * 128u + (unsigned)tid;     // 0 .. 1M-1
    unsigned b   = gid >> 16;
    unsigned pos = gid & 65535u;                          // h*256 + w
    unsigned wpos = (blockIdx.x * 128u + warp * 32u) & 65535u;  // warp-uniform
    const float* src_w = dct + (size_t)b * 64u * HW + wpos;

    uint32_t sb = (uint32_t)__cvta_generic_to_shared(sbuf);

    // ---- Warp-private prefetch (identical geometry to the 86.3us kernel):
    // warp w copies the 64 x 128B segments covering positions [32w, 32w+32)
    // across all channels. Per chunk: 64 x 16B units, 2 per lane.
    // Unit m: channel c*8 + (m>>3), float col (m&7)*4 of the warp stripe. ----
    #pragma unroll
    for (int c = 0; c < 8; c++) {
        #pragma unroll
        for (int k = 0; k < 2; k++) {
            int m = lane + k * 32;
            const float* g = src_w + (size_t)(c * 8 + (m >> 3)) * HW + (m & 7) * 4;
            cp_async16(sb + (uint32_t)((c * 1024 + (m >> 3) * 128 + warp * 32 + (m & 7) * 4) * 4), g);
        }
        cp_commit();
    }

    // ---- Tables (overlap with copies); one barrier, doesn't drain groups ----
    if (tid < 64) {
        int u = tid >> 3, x = tid & 7;
        float c = (u == 0) ? 0.70710678118654752440f : 1.0f;
        float h = cospif((float)((2 * x + 1) * u) * (1.0f / 16.0f));
        float v = 0.5f * c * h;
        if (x < 4) {
            s_hx[u * 4 + x] = v;
            s_hy[u * 4 + x] = v * (1.0f / 255.0f);
        }
        s_std[tid]  = std_[tid];
        s_mean[tid] = mean_[tid];
    }
    __syncthreads();

    // ---- Accumulators: rows xp = E+O, rows 7-xp = E-O. K folded into E. ----
    const float K = 128.0f / 255.0f;
    float E[4][8], O[4][8];
    #pragma unroll
    for (int xp = 0; xp < 4; xp++)
        #pragma unroll
        for (int y = 0; y < 8; y++) { E[xp][y] = K; O[xp][y] = 0.0f; }

    consume_chunk<0>(sbuf, s_hx, s_hy, s_std, s_mean, tid, E, O);
    consume_chunk<1>(sbuf, s_hx, s_hy, s_std, s_mean, tid, E, O);
    consume_chunk<2>(sbuf, s_hx, s_hy, s_std, s_mean, tid, E, O);
    consume_chunk<3>(sbuf, s_hx, s_hy, s_std, s_mean, tid, E, O);
    consume_chunk<4>(sbuf, s_hx, s_hy, s_std, s_mean, tid, E, O);
    consume_chunk<5>(sbuf, s_hx, s_hy, s_std, s_mean, tid, E, O);
    consume_chunk<6>(sbuf, s_hx, s_hy, s_std, s_mean, tid, E, O);
    consume_chunk<7>(sbuf, s_hx, s_hy, s_std, s_mean, tid, E, O);

    // ---- Write 8x8 pixel block: two streaming STG.128 per row ----
    unsigned hh = pos >> 8, ww = pos & 255u;
    float* dst = out + (size_t)b * ((size_t)OUTW * OUTW)
                     + (size_t)hh * 8 * OUTW + (size_t)ww * 8;

    #pragma unroll
    for (int xp = 0; xp < 4; xp++) {
        float4 a, bq;
        a.x  = E[xp][0] + O[xp][0];  a.y  = E[xp][1] + O[xp][1];
        a.z  = E[xp][2] + O[xp][2];  a.w  = E[xp][3] + O[xp][3];
        bq.x = E[xp][4] + O[xp][4];  bq.y = E[xp][5] + O[xp][5];
        bq.z = E[xp][6] + O[xp][6];  bq.w = E[xp][7] + O[xp][7];
        __stcs((float4*)(dst + (size_t)xp * OUTW),     a);
        __stcs((float4*)(dst + (size_t)xp * OUTW + 4), bq);

        float4 c4, d4;
        c4.x = E[xp][0] - O[xp][0];  c4.y = E[xp][1] - O[xp][1];
        c4.z = E[xp][2] - O[xp][2];  c4.w = E[xp][3] - O[xp][3];
        d4.x = E[xp][4] - O[xp][4];  d4.y = E[xp][5] - O[xp][5];
        d4.z = E[xp][6] - O[xp][6];  d4.w = E[xp][7] - O[xp][7];
        __stcs((float4*)(dst + (size_t)(7 - xp) * OUTW),     c4);
        __stcs((float4*)(dst + (size_t)(7 - xp) * OUTW + 4), d4);
    }
}

extern "C" void kernel_launch(void* const* d_in, const int* in_sizes, int n_in,
                              void* d_out, int out_size)
{
    (void)in_sizes; (void)n_in; (void)out_size;
    const float* dct   = (const float*)d_in[0];
    const float* mean_ = (const float*)d_in[1];
    const float* std_  = (const float*)d_in[2];
    float* out = (float*)d_out;

    static bool attr_set = false;
    if (!attr_set) {
        cudaFuncSetAttribute(idct_kernel,
                             cudaFuncAttributeMaxDynamicSharedMemorySize,
                             SMEM_BYTES);
        attr_set = true;
    }
    // 1,048,576 blocks of 8x8 pixels, 1 thread each; 128 per CTA.
    idct_kernel<<<8192, 128, SMEM_BYTES>>>(dct, mean_, std_, out);
}

// round 17
// speedup vs baseline: 1.3247x; 1.0195x over previous
#include <cuda_runtime.h>
#include <cstdint>

// dct: [16, 64, 256, 256] fp32, mean/std: [64] fp32, out: [16, 1, 2048, 2048] fp32
#define HW      65536        // 256*256
#define OUTW    2048

// CTA: 64 threads, 64 positions. Dynamic smem (floats):
//   sbuf [8 chunks][8 ch][64 pos] + tables
#define SBUF_FLOATS   4096
#define SMEM_FLOATS   (SBUF_FLOATS + 192)
#define SMEM_BYTES    (SMEM_FLOATS * 4)

__device__ __forceinline__ void cp_async16(uint32_t dst, const void* src) {
    asm volatile("cp.async.cg.shared.global [%0], [%1], 16;" :: "r"(dst), "l"(src));
}
__device__ __forceinline__ void cp_commit() {
    asm volatile("cp.async.commit_group;");
}
template <int N>
__device__ __forceinline__ void cp_wait() {
    asm volatile("cp.async.wait_group %0;" :: "n"(N) : "memory");
}

// Consume chunk U (warp-local ordering only: wait_group + syncwarp).
template <int U>
__device__ __forceinline__ void consume_chunk(
    const float* sbuf, const float* s_hx, const float* s_hy,
    const float* s_std, const float* s_mean,
    int tid, float E[4][8], float O[4][8])
{
    cp_wait<7 - U>();
    __syncwarp();      // cross-lane visibility within the warp's stripe

    float t[8];
    #pragma unroll
    for (int v = 0; v < 8; v++)
        t[v] = fmaf(sbuf[U * 512 + v * 64 + tid],
                    s_std[U * 8 + v], s_mean[U * 8 + v]);

    float ty[8];
    #pragma unroll
    for (int yp = 0; yp < 4; yp++) {
        float te = 0.0f, to = 0.0f;
        #pragma unroll
        for (int vp = 0; vp < 4; vp++) {
            te = fmaf(s_hy[(2 * vp    ) * 4 + yp], t[2 * vp    ], te);
            to = fmaf(s_hy[(2 * vp + 1) * 4 + yp], t[2 * vp + 1], to);
        }
        ty[yp]     = te + to;
        ty[7 - yp] = te - to;
    }

    #pragma unroll
    for (int xp = 0; xp < 4; xp++) {
        float w = s_hx[U * 4 + xp];
        if ((U & 1) == 0) {
            #pragma unroll
            for (int y = 0; y < 8; y++) E[xp][y] = fmaf(w, ty[y], E[xp][y]);
        } else {
            #pragma unroll
            for (int y = 0; y < 8; y++) O[xp][y] = fmaf(w, ty[y], O[xp][y]);
        }
    }
}

__global__ __launch_bounds__(64, 8) void idct_kernel(
    const float* __restrict__ dct,
    const float* __restrict__ mean_,
    const float* __restrict__ std_,
    float* __restrict__ out)
{
    extern __shared__ float smem[];
    float* sbuf   = smem;                      // [8][8][64]
    float* s_hx   = smem + SBUF_FLOATS;        // [8][4]
    float* s_hy   = s_hx + 32;                 // [8][4]
    float* s_std  = s_hy + 32;                 // [64]
    float* s_mean = s_std + 64;                // [64]

    int tid  = threadIdx.x;
    int warp = tid >> 5, lane = tid & 31;

    unsigned gid = blockIdx.x * 64u + (unsigned)tid;      // 0 .. 1M-1
    unsigned b   = gid >> 16;
    unsigned pos = gid & 65535u;                          // h*256 + w
    unsigned wpos = (blockIdx.x * 64u + warp * 32u) & 65535u;   // warp-uniform
    const float* src_w = dct + (size_t)b * 64u * HW + wpos;

    uint32_t sb = (uint32_t)__cvta_generic_to_shared(sbuf);

    // ---- Warp-private prefetch (identical geometry to the 85.5us kernel):
    // warp w copies the 64 x 128B segments covering positions [32w, 32w+32)
    // across all channels. Per chunk: 64 x 16B units, 2 per lane.
    // Unit m: channel c*8 + (m>>3), float col (m&7)*4 of the warp stripe. ----
    #pragma unroll
    for (int c = 0; c < 8; c++) {
        #pragma unroll
        for (int k = 0; k < 2; k++) {
            int m = lane + k * 32;
            const float* g = src_w + (size_t)(c * 8 + (m >> 3)) * HW + (m & 7) * 4;
            cp_async16(sb + (uint32_t)((c * 512 + (m >> 3) * 64 + warp * 32 + (m & 7) * 4) * 4), g);
        }
        cp_commit();
    }

    // ---- Tables (overlap with copies); one barrier, doesn't drain groups ----
    {
        int u = tid >> 3, x = tid & 7;
        float c = (u == 0) ? 0.70710678118654752440f : 1.0f;
        float h = cospif((float)((2 * x + 1) * u) * (1.0f / 16.0f));
        float v = 0.5f * c * h;
        if (x < 4) {
            s_hx[u * 4 + x] = v;
            s_hy[u * 4 + x] = v * (1.0f / 255.0f);
        }
        s_std[tid]  = std_[tid];
        s_mean[tid] = mean_[tid];
    }
    __syncthreads();

    // ---- Accumulators: rows xp = E+O, rows 7-xp = E-O. K folded into E. ----
    const float K = 128.0f / 255.0f;
    float E[4][8], O[4][8];
    #pragma unroll
    for (int xp = 0; xp < 4; xp++)
        #pragma unroll
        for (int y = 0; y < 8; y++) { E[xp][y] = K; O[xp][y] = 0.0f; }

    consume_chunk<0>(sbuf, s_hx, s_hy, s_std, s_mean, tid, E, O);
    consume_chunk<1>(sbuf, s_hx, s_hy, s_std, s_mean, tid, E, O);
    consume_chunk<2>(sbuf, s_hx, s_hy, s_std, s_mean, tid, E, O);
    consume_chunk<3>(sbuf, s_hx, s_hy, s_std, s_mean, tid, E, O);
    consume_chunk<4>(sbuf, s_hx, s_hy, s_std, s_mean, tid, E, O);
    consume_chunk<5>(sbuf, s_hx, s_hy, s_std, s_mean, tid, E, O);
    consume_chunk<6>(sbuf, s_hx, s_hy, s_std, s_mean, tid, E, O);
    consume_chunk<7>(sbuf, s_hx, s_hy, s_std, s_mean, tid, E, O);

    // ---- Write 8x8 pixel block: two streaming STG.128 per row ----
    unsigned hh = pos >> 8, ww = pos & 255u;
    float* dst = out + (size_t)b * ((size_t)OUTW * OUTW)
                     + (size_t)hh * 8 * OUTW + (size_t)ww * 8;

    #pragma unroll
    for (int xp = 0; xp < 4; xp++) {
        float4 a, bq;
        a.x  = E[xp][0] + O[xp][0];  a.y  = E[xp][1] + O[xp][1];
        a.z  = E[xp][2] + O[xp][2];  a.w  = E[xp][3] + O[xp][3];
        bq.x = E[xp][4] + O[xp][4];  bq.y = E[xp][5] + O[xp][5];
        bq.z = E[xp][6] + O[xp][6];  bq.w = E[xp][7] + O[xp][7];
        __stcs((float4*)(dst + (size_t)xp * OUTW),     a);
        __stcs((float4*)(dst + (size_t)xp * OUTW + 4), bq);

        float4 c4, d4;
        c4.x = E[xp][0] - O[xp][0];  c4.y = E[xp][1] - O[xp][1];
        c4.z = E[xp][2] - O[xp][2];  c4.w = E[xp][3] - O[xp][3];
        d4.x = E[xp][4] - O[xp][4];  d4.y = E[xp][5] - O[xp][5];
        d4.z = E[xp][6] - O[xp][6];  d4.w = E[xp][7] - O[xp][7];
        __stcs((float4*)(dst + (size_t)(7 - xp) * OUTW),     c4);
        __stcs((float4*)(dst + (size_t)(7 - xp) * OUTW + 4), d4);
    }
}

extern "C" void kernel_launch(void* const* d_in, const int* in_sizes, int n_in,
                              void* d_out, int out_size)
{
    (void)in_sizes; (void)n_in; (void)out_size;
    const float* dct   = (const float*)d_in[0];
    const float* mean_ = (const float*)d_in[1];
    const float* std_  = (const float*)d_in[2];
    float* out = (float*)d_out;

    static bool attr_set = false;
    if (!attr_set) {
        cudaFuncSetAttribute(idct_kernel,
                             cudaFuncAttributeMaxDynamicSharedMemorySize,
                             SMEM_BYTES);
        attr_set = true;
    }
    // 1,048,576 blocks of 8x8 pixels, 1 thread each; 64 per CTA.
    idct_kernel<<<16384, 64, SMEM_BYTES>>>(dct, mean_, std_, out);
}